// round 13
// baseline (speedup 1.0000x reference)
#include <cuda_runtime.h>
#include <cstdint>

#define DD    2048
#define NBLK  16
#define BATCH 32

// Scratch (no allocations allowed): all reset by protocol each launch
__device__ float g_part[BATCH * 4 * NBLK];   // gate logit partials
__device__ int   g_arrive = 0;               // gate-CTA arrival counter
__device__ int   g_done   = 0;               // whole-grid completion counter
__device__ volatile int g_ready = 0;         // gates-finalized flag
__device__ int   g_cnt[NBLK];
__device__ int   g_idx[NBLK * 32];
__device__ float g_gval[NBLK * 32];

__device__ __forceinline__ unsigned long long ffma2(
    unsigned long long a, unsigned long long b, unsigned long long c)
{
    unsigned long long d;
    asm("fma.rn.f32x2 %0, %1, %2, %3;" : "=l"(d) : "l"(a), "l"(b), "l"(c));
    return d;
}
__device__ __forceinline__ void cpa16(unsigned int dst, const void* src)
{
    asm volatile("cp.async.cg.shared.global [%0], [%1], 16;"
                 :: "r"(dst), "l"(src));
}
__device__ __forceinline__ void cp_commit()
{
    asm volatile("cp.async.commit_group;" ::: "memory");
}
__device__ __forceinline__ void cp_wait(int n)
{
    switch (n) {
    case 0: asm volatile("cp.async.wait_group 0;" ::: "memory"); break;
    case 1: asm volatile("cp.async.wait_group 1;" ::: "memory"); break;
    case 2: asm volatile("cp.async.wait_group 2;" ::: "memory"); break;
    default: asm volatile("cp.async.wait_group 3;" ::: "memory"); break;
    }
}

// Issue W stage s (k-steps 2s, 2s+1) into slot s&3. One commit group per stage.
__device__ __forceinline__ void issue_stage(
    unsigned int wb, const char* Wrow0, int s, int tid)
{
    const int slot = s & 3;
#pragma unroll
    for (int q = 0; q < 2; q++) {
        const int t = 2 * s + q;
#pragma unroll
        for (int h = 0; h < 2; h++) {
            const int chunk = tid + h * 512;
            const int row   = chunk >> 5;
            const int off   = (chunk & 31) * 16;
            cpa16(wb + slot * 32768 + q * 16384 + row * 512 + off,
                  Wrow0 + (size_t)row * 8192 + (size_t)t * 512 + off);
        }
    }
    cp_commit();
}

// ---------------------------------------------------------------------------
// ONE fused kernel. grid=256, block=512, 1 CTA/SM.
//  - all CTAs: issue depth-4 cp.async W prefetch keyed on blockIdx only
//  - CTAs 0..127: gate partials (b=bid>>2, slice=bid&3) + bias fill;
//    last arrival finalizes gates + compaction, releases g_ready
//  - all CTAs: spin on g_ready, then gated GEMM (tile=bid&63, chunk=bid>>6)
// ---------------------------------------------------------------------------
__global__ __launch_bounds__(512, 1) void fused_kernel(
    const float* __restrict__ x, const float* __restrict__ gw,
    const float* __restrict__ gb, const float* __restrict__ W,
    const float* __restrict__ bias, float* __restrict__ out)
{
    extern __shared__ float smem[];
    float* xs = smem;                                  // 8 x 2048 floats (64 KB)
    char*  wsm = (char*)smem + 65536;                  // W stages: 4 x 32 KB
    const unsigned int wb =
        (unsigned int)__cvta_generic_to_shared(wsm);
    float* red = (float*)wsm;                          // aliased after loop

    const int bid  = blockIdx.x;
    const int tid  = threadIdx.x;
    const int tile = bid & 63;
    const int chnk = bid >> 6;                         // 0..3
    const int nb   = tile >> 2;
    const int c0   = tile * 32;
    const int s0   = chnk * 8;

    // ---- W prefetch prologue: 4 stages, independent of gates ----
    const char* Wrow0 = (const char*)W + (size_t)c0 * 8192;
#pragma unroll
    for (int s = 0; s < 4; s++) issue_stage(wb, Wrow0, s, tid);

    // ---- gate phase (CTAs 0..127) ----
    __shared__ float ws[16][NBLK + 1];
    __shared__ float sgate[BATCH][NBLK + 1];
    __shared__ int   lastflag;
    if (tid == 0) lastflag = 0;

    if (bid < 128) {
        const int b  = bid >> 2;
        const int sl = bid & 3;
        const int k  = sl * 512 + tid;

        // bias fill for this (b, slice) range: 512 floats = 128 float4
        if (tid < 128)
            ((float4*)(out + (size_t)b * DD + sl * 512))[tid] =
                ((const float4*)(bias + sl * 512))[tid];

        float p[NBLK];
        {
            const float xv = x[(size_t)b * DD + k];
            const float4* gr = (const float4*)(gw + (size_t)k * NBLK);
            const float4 w0 = gr[0], w1 = gr[1], w2 = gr[2], w3 = gr[3];
            p[0]=xv*w0.x;  p[1]=xv*w0.y;  p[2]=xv*w0.z;  p[3]=xv*w0.w;
            p[4]=xv*w1.x;  p[5]=xv*w1.y;  p[6]=xv*w1.z;  p[7]=xv*w1.w;
            p[8]=xv*w2.x;  p[9]=xv*w2.y;  p[10]=xv*w2.z; p[11]=xv*w2.w;
            p[12]=xv*w3.x; p[13]=xv*w3.y; p[14]=xv*w3.z; p[15]=xv*w3.w;
        }
#pragma unroll
        for (int j = 0; j < NBLK; j++)
#pragma unroll
            for (int off = 16; off > 0; off >>= 1)
                p[j] += __shfl_xor_sync(0xffffffffu, p[j], off);

        if ((tid & 31) == 0) {
#pragma unroll
            for (int j = 0; j < NBLK; j++) ws[tid >> 5][j] = p[j];
        }
        __syncthreads();
        if (tid < NBLK) {
            float s = 0.f;
#pragma unroll
            for (int w = 0; w < 16; w++) s += ws[w][tid];
            g_part[((size_t)b * 4 + sl) * NBLK + tid] = s;
        }
        __syncthreads();
        if (tid == 0) {
            __threadfence();
            if (atomicAdd(&g_arrive, 1) == 127) lastflag = 1;
        }
        __syncthreads();

        if (lastflag) {                      // ---- finalize gates ----
            __threadfence();
            if (tid < BATCH) {
                float v[NBLK];
                const float4* gb4 = (const float4*)gb;
                {
                    const float4 b0 = gb4[0], b1 = gb4[1], b2 = gb4[2], b3 = gb4[3];
                    v[0]=b0.x;  v[1]=b0.y;  v[2]=b0.z;  v[3]=b0.w;
                    v[4]=b1.x;  v[5]=b1.y;  v[6]=b1.z;  v[7]=b1.w;
                    v[8]=b2.x;  v[9]=b2.y;  v[10]=b2.z; v[11]=b2.w;
                    v[12]=b3.x; v[13]=b3.y; v[14]=b3.z; v[15]=b3.w;
                }
#pragma unroll
                for (int s = 0; s < 4; s++) {
                    const float4* pp =
                        (const float4*)(g_part + ((size_t)tid * 4 + s) * NBLK);
                    const float4 p0 = pp[0], p1 = pp[1], p2 = pp[2], p3 = pp[3];
                    v[0]+=p0.x;  v[1]+=p0.y;  v[2]+=p0.z;  v[3]+=p0.w;
                    v[4]+=p1.x;  v[5]+=p1.y;  v[6]+=p1.z;  v[7]+=p1.w;
                    v[8]+=p2.x;  v[9]+=p2.y;  v[10]+=p2.z; v[11]+=p2.w;
                    v[12]+=p3.x; v[13]+=p3.y; v[14]+=p3.z; v[15]+=p3.w;
                }
#pragma unroll
                for (int j = 0; j < NBLK; j++) v[j] = 1.f / (1.f + expf(-v[j]));

                unsigned mask = 0;   // drop 8 smallest; '<' => lowest idx on ties
                for (int it = 0; it < NBLK / 2; it++) {
                    int best = 0; float bv = 3.4e38f;
                    for (int j = 0; j < NBLK; j++)
                        if (!((mask >> j) & 1u) && v[j] < bv) { bv = v[j]; best = j; }
                    mask |= 1u << best;
                }
#pragma unroll
                for (int j = 0; j < NBLK; j++)
                    sgate[tid][j] = ((mask >> j) & 1u) ? 0.f : v[j];
            }
            __syncthreads();
            if (tid < 32) {                  // warp 0: compaction
                const int lane = tid;
                if (lane < NBLK) {
                    int cnt = 0;
                    for (int bb = 0; bb < BATCH; bb++) {
                        const float v = sgate[bb][lane];
                        if (v != 0.f) {
                            g_idx[lane * 32 + cnt] = bb;
                            g_gval[lane * 32 + cnt] = v; cnt++;
                        }
                    }
                    g_cnt[lane] = cnt;
                    for (int s = cnt; s < 32; s++) {
                        g_idx[lane * 32 + s] = 0; g_gval[lane * 32 + s] = 0.f;
                    }
                }
                if (lane == 0) { g_arrive = 0; __threadfence(); g_ready = 1; }
            }
        }
    }

    // ---- spin until gates ready (finalizer is wave-1 resident -> no deadlock)
    if (tid == 0) {
        while (g_ready == 0) __nanosleep(40);
    }
    __syncthreads();
    __threadfence();

    __shared__ int   s_bidx[8];
    __shared__ float s_gvl[8];
    __shared__ int   s_cnt;
    if (tid < 8) {
        s_bidx[tid] = g_idx[nb * 32 + s0 + tid];   // padded slots: b=0
        s_gvl[tid]  = g_gval[nb * 32 + s0 + tid];
        if (tid == 0) s_cnt = g_cnt[nb];
    }
    __syncthreads();
    const int cnt = s_cnt;

    if (s0 >= cnt) {                         // idle chunk: drain + exit
        cp_wait(0);
        __syncthreads();
        if (tid == 0) {
            __threadfence();
            if (atomicAdd(&g_done, 1) == (int)gridDim.x - 1) {
                g_done = 0; g_ready = 0;
            }
        }
        return;
    }

    int bidx[8];
#pragma unroll
    for (int j = 0; j < 8; j++) bidx[j] = s_bidx[j];

    // stage x rows (coalesced float4)
    for (int m = tid; m < 4096; m += 512) {
        const int s  = m >> 9;
        const int k4 = m & 511;
        ((float4*)(xs + s * DD))[k4] = ((const float4*)(x + (size_t)bidx[s] * DD))[k4];
    }

    const int kg = tid & 63;
    const int cg = tid >> 6;

    unsigned long long acc[8][4];
#pragma unroll
    for (int s = 0; s < 8; s++)
#pragma unroll
        for (int c = 0; c < 4; c++) acc[s][c] = 0ull;

#pragma unroll
    for (int j = 0; j < 8; j++) {            // 8 super-iters x 2 k-steps
        cp_wait(j <= 4 ? 3 : 7 - j);
        __syncthreads();
#pragma unroll
        for (int q = 0; q < 2; q++) {
            const int t    = 2 * j + q;
            const int kidx = kg + t * 64;
            const char* wsb = wsm + (j & 3) * 32768 + q * 16384 + cg * 2048 + kg * 8;

            unsigned long long wv[4];
#pragma unroll
            for (int c = 0; c < 4; c++)
                wv[c] = *(const unsigned long long*)(wsb + c * 512);

            unsigned long long xv[4];
#pragma unroll
            for (int s = 0; s < 4; s++)
                xv[s] = *(const unsigned long long*)(xs + s * DD + (kidx << 1));
#pragma unroll
            for (int c = 0; c < 4; c++)
#pragma unroll
                for (int s = 0; s < 4; s++)
                    acc[s][c] = ffma2(xv[s], wv[c], acc[s][c]);
#pragma unroll
            for (int s = 0; s < 4; s++)
                xv[s] = *(const unsigned long long*)(xs + (s + 4) * DD + (kidx << 1));
#pragma unroll
            for (int c = 0; c < 4; c++)
#pragma unroll
                for (int s = 0; s < 4; s++)
                    acc[s + 4][c] = ffma2(xv[s], wv[c], acc[s + 4][c]);
        }
        __syncthreads();
        if (j < 4) issue_stage(wb, Wrow0, j + 4, tid);
    }

    // horizontal add (even-k + odd-k), conflict-free partial store into red
    // (aliases W stage memory, dead now): bank (idx + kg) % 32, all distinct
#pragma unroll
    for (int s = 0; s < 8; s++) {
#pragma unroll
        for (int c = 0; c < 4; c++) {
            const unsigned long long v = acc[s][c];
            const float lo = __uint_as_float((unsigned)(v & 0xffffffffu));
            const float hi = __uint_as_float((unsigned)(v >> 32));
            red[(s * 32 + cg * 4 + c) * 65 + kg] = lo + hi;
        }
    }
    __syncthreads();

    if (tid < 256) {
        const int s  = tid >> 5;
        const int cp = tid & 31;
        const float* r = red + tid * 65;
        float a0 = 0.f, a1 = 0.f, a2 = 0.f, a3 = 0.f;
#pragma unroll
        for (int k = 0; k < 64; k += 4) {
            a0 += r[k]; a1 += r[k + 1]; a2 += r[k + 2]; a3 += r[k + 3];
        }
        const float sum = (a0 + a1) + (a2 + a3);
        if (s0 + s < cnt)
            out[(size_t)s_bidx[s] * DD + c0 + cp] = s_gvl[s] * sum + bias[c0 + cp];
    }
    __syncthreads();

    if (tid == 0) {                          // completion + counter reset
        __threadfence();
        if (atomicAdd(&g_done, 1) == (int)gridDim.x - 1) {
            g_done = 0; g_ready = 0;
        }
    }
}

// ---------------------------------------------------------------------------
extern "C" void kernel_launch(void* const* d_in, const int* in_sizes, int n_in,
                              void* d_out, int out_size)
{
    (void)in_sizes; (void)n_in; (void)out_size;
    const float* x    = (const float*)d_in[0];
    const float* gw   = (const float*)d_in[1];
    const float* gb   = (const float*)d_in[2];
    const float* W    = (const float*)d_in[3];
    const float* bias = (const float*)d_in[4];
    float* out = (float*)d_out;

    static int smem_set = 0;
    if (!smem_set) {
        cudaFuncSetAttribute(fused_kernel,
                             cudaFuncAttributeMaxDynamicSharedMemorySize,
                             196608);        // 64 KB xs + 128 KB W stages
        smem_set = 1;
    }

    fused_kernel<<<256, 512, 196608>>>(x, gw, gb, W, bias, out);
}

// round 14
// speedup vs baseline: 1.4465x; 1.4465x over previous
#include <cuda_runtime.h>
#include <cstdint>

#define DD    2048
#define NBLK  16
#define BATCH 32

// Scratch (no allocations allowed -> __device__ globals; protocol-reset)
__device__ float g_part[BATCH * 4 * NBLK];   // gate logit partials
__device__ int   g_arrive = 0;               // arrival counter (reset by finalize)
__device__ int   g_cnt[NBLK];
__device__ int   g_idx[NBLK * 32];
__device__ float g_gval[NBLK * 32];

// ---------------------------------------------------------------------------
// Kernel 1: gate logit partials, K split 4 ways. grid=(32 batches, 4 slices).
// Bias-fills out. Last-arriving CTA finalizes gates + compaction. (Proven R12.)
// ---------------------------------------------------------------------------
__global__ __launch_bounds__(256) void gate_kernel(
    const float* __restrict__ x, const float* __restrict__ gw,
    const float* __restrict__ gb, const float* __restrict__ bias,
    float* __restrict__ out)
{
    const int b    = blockIdx.x;
    const int sl   = blockIdx.y;
    const int tid  = threadIdx.x;
    const int base = sl * 512;

    __shared__ int lastflag;
    if (tid == 0) lastflag = 0;

    if (tid < 128)
        ((float4*)(out + (size_t)b * DD + base))[tid] = ((const float4*)(bias + base))[tid];

    float p[NBLK];
#pragma unroll
    for (int j = 0; j < NBLK; j++) p[j] = 0.f;

#pragma unroll
    for (int r = 0; r < 2; r++) {
        const int k = base + r * 256 + tid;
        const float xv = x[(size_t)b * DD + k];
        const float4* gr = (const float4*)(gw + (size_t)k * NBLK);
        const float4 w0 = gr[0], w1 = gr[1], w2 = gr[2], w3 = gr[3];
        p[0]  += xv * w0.x;  p[1]  += xv * w0.y;  p[2]  += xv * w0.z;  p[3]  += xv * w0.w;
        p[4]  += xv * w1.x;  p[5]  += xv * w1.y;  p[6]  += xv * w1.z;  p[7]  += xv * w1.w;
        p[8]  += xv * w2.x;  p[9]  += xv * w2.y;  p[10] += xv * w2.z;  p[11] += xv * w2.w;
        p[12] += xv * w3.x;  p[13] += xv * w3.y;  p[14] += xv * w3.z;  p[15] += xv * w3.w;
    }

#pragma unroll
    for (int j = 0; j < NBLK; j++)
#pragma unroll
        for (int off = 16; off > 0; off >>= 1)
            p[j] += __shfl_xor_sync(0xffffffffu, p[j], off);

    __shared__ float ws[8][NBLK + 1];
    if ((tid & 31) == 0) {
#pragma unroll
        for (int j = 0; j < NBLK; j++) ws[tid >> 5][j] = p[j];
    }
    __syncthreads();

    if (tid < NBLK) {
        float s = 0.f;
#pragma unroll
        for (int w = 0; w < 8; w++) s += ws[w][tid];
        g_part[((size_t)b * 4 + sl) * NBLK + tid] = s;
    }
    __syncthreads();

    if (tid == 0) {
        __threadfence();
        if (atomicAdd(&g_arrive, 1) == 127) lastflag = 1;
    }
    __syncthreads();
    if (!lastflag) return;
    __threadfence();

    __shared__ float sgate[BATCH][NBLK + 1];
    if (tid < BATCH) {
        float v[NBLK];
        const float4* gb4 = (const float4*)gb;
        {
            const float4 b0 = gb4[0], b1 = gb4[1], b2 = gb4[2], b3 = gb4[3];
            v[0]=b0.x;  v[1]=b0.y;  v[2]=b0.z;  v[3]=b0.w;
            v[4]=b1.x;  v[5]=b1.y;  v[6]=b1.z;  v[7]=b1.w;
            v[8]=b2.x;  v[9]=b2.y;  v[10]=b2.z; v[11]=b2.w;
            v[12]=b3.x; v[13]=b3.y; v[14]=b3.z; v[15]=b3.w;
        }
#pragma unroll
        for (int s = 0; s < 4; s++) {
            const float4* pp = (const float4*)(g_part + ((size_t)tid * 4 + s) * NBLK);
            const float4 p0 = pp[0], p1 = pp[1], p2 = pp[2], p3 = pp[3];
            v[0]+=p0.x;  v[1]+=p0.y;  v[2]+=p0.z;  v[3]+=p0.w;
            v[4]+=p1.x;  v[5]+=p1.y;  v[6]+=p1.z;  v[7]+=p1.w;
            v[8]+=p2.x;  v[9]+=p2.y;  v[10]+=p2.z; v[11]+=p2.w;
            v[12]+=p3.x; v[13]+=p3.y; v[14]+=p3.z; v[15]+=p3.w;
        }
#pragma unroll
        for (int j = 0; j < NBLK; j++) v[j] = 1.f / (1.f + expf(-v[j]));

        unsigned mask = 0;   // drop 8 smallest; '<' => lowest index wins ties
        for (int it = 0; it < NBLK / 2; it++) {
            int best = 0; float bv = 3.4e38f;
            for (int j = 0; j < NBLK; j++)
                if (!((mask >> j) & 1u) && v[j] < bv) { bv = v[j]; best = j; }
            mask |= 1u << best;
        }
#pragma unroll
        for (int j = 0; j < NBLK; j++)
            sgate[tid][j] = ((mask >> j) & 1u) ? 0.f : v[j];
    }
    __syncthreads();

    if (tid < 32) {
        const int lane = tid;
        if (lane < NBLK) {
            int cnt = 0;
            for (int bb = 0; bb < BATCH; bb++) {
                const float v = sgate[bb][lane];
                if (v != 0.f) { g_idx[lane * 32 + cnt] = bb; g_gval[lane * 32 + cnt] = v; cnt++; }
            }
            g_cnt[lane] = cnt;
            for (int s = cnt; s < 32; s++) { g_idx[lane * 32 + s] = 0; g_gval[lane * 32 + s] = 0.f; }
        }
        if (lane == 0) g_arrive = 0;         // reset for next graph replay
    }
}

// ---------------------------------------------------------------------------
// Kernel 2: gated skinny GEMM; W streamed via cp.async (4 stages x 32 KB).
// grid=256: tile = bid&63 (32 rows), chunk = bid>>6 (8 compacted slots).
// Idle CTAs exit BEFORE issuing any prefetch.
// ---------------------------------------------------------------------------
__device__ __forceinline__ unsigned long long ffma2(
    unsigned long long a, unsigned long long b, unsigned long long c)
{
    unsigned long long d;
    asm("fma.rn.f32x2 %0, %1, %2, %3;" : "=l"(d) : "l"(a), "l"(b), "l"(c));
    return d;
}
__device__ __forceinline__ void cpa16(unsigned int dst, const void* src)
{
    asm volatile("cp.async.cg.shared.global [%0], [%1], 16;" :: "r"(dst), "l"(src));
}
__device__ __forceinline__ void cp_commit()
{
    asm volatile("cp.async.commit_group;" ::: "memory");
}
__device__ __forceinline__ void cp_wait(int n)
{
    switch (n) {
    case 0: asm volatile("cp.async.wait_group 0;" ::: "memory"); break;
    case 1: asm volatile("cp.async.wait_group 1;" ::: "memory"); break;
    case 2: asm volatile("cp.async.wait_group 2;" ::: "memory"); break;
    default: asm volatile("cp.async.wait_group 3;" ::: "memory"); break;
    }
}

// Issue W stage s (k-steps 2s, 2s+1) into slot s&3. One commit group per stage.
__device__ __forceinline__ void issue_stage(
    unsigned int wb, const char* Wrow0, int s, int tid)
{
    const int slot = s & 3;
#pragma unroll
    for (int q = 0; q < 2; q++) {
        const int t = 2 * s + q;
#pragma unroll
        for (int h = 0; h < 2; h++) {
            const int chunk = tid + h * 512;
            const int row   = chunk >> 5;
            const int off   = (chunk & 31) * 16;
            cpa16(wb + slot * 32768 + q * 16384 + row * 512 + off,
                  Wrow0 + (size_t)row * 8192 + (size_t)t * 512 + off);
        }
    }
    cp_commit();
}

__global__ __launch_bounds__(512, 1) void main_kernel(
    const float* __restrict__ x, const float* __restrict__ W,
    const float* __restrict__ bias, float* __restrict__ out)
{
    extern __shared__ float smem[];
    float* xs  = smem;                                 // 8 x 2048 floats (64 KB)
    char*  wsm = (char*)smem + 65536;                  // W stages: 4 x 32 KB
    const unsigned int wb = (unsigned int)__cvta_generic_to_shared(wsm);
    float* red = (float*)wsm;                          // aliased after loop

    const int bid  = blockIdx.x;
    const int tid  = threadIdx.x;
    const int tile = bid & 63;
    const int chnk = bid >> 6;
    const int nb   = tile >> 2;
    const int c0   = tile * 32;
    const int s0   = chnk * 8;

    __shared__ int   s_bidx[8];
    __shared__ float s_gvl[8];
    __shared__ int   s_cnt;
    if (tid < 8) {
        s_bidx[tid] = g_idx[nb * 32 + s0 + tid];       // padded slots: b=0
        s_gvl[tid]  = g_gval[nb * 32 + s0 + tid];
        if (tid == 0) s_cnt = g_cnt[nb];
    }
    __syncthreads();
    const int cnt = s_cnt;
    if (s0 >= cnt) return;                             // idle: no prefetch issued

    // ---- W prefetch prologue: 4 stages via cp.async ----
    const char* Wrow0 = (const char*)W + (size_t)c0 * 8192;
#pragma unroll
    for (int s = 0; s < 4; s++) issue_stage(wb, Wrow0, s, tid);

    int bidx[8];
#pragma unroll
    for (int j = 0; j < 8; j++) bidx[j] = s_bidx[j];

    // stage x rows (coalesced float4; overlaps in-flight cp.async)
    for (int m = tid; m < 4096; m += 512) {
        const int s  = m >> 9;
        const int k4 = m & 511;
        ((float4*)(xs + s * DD))[k4] = ((const float4*)(x + (size_t)bidx[s] * DD))[k4];
    }

    const int kg = tid & 63;
    const int cg = tid >> 6;

    unsigned long long acc[8][4];
#pragma unroll
    for (int s = 0; s < 8; s++)
#pragma unroll
        for (int c = 0; c < 4; c++) acc[s][c] = 0ull;

#pragma unroll
    for (int j = 0; j < 8; j++) {            // 8 super-iters x 2 k-steps
        cp_wait(j <= 4 ? 3 : 7 - j);
        __syncthreads();
#pragma unroll
        for (int q = 0; q < 2; q++) {
            const int t    = 2 * j + q;
            const int kidx = kg + t * 64;
            const char* wsb = wsm + (j & 3) * 32768 + q * 16384 + cg * 2048 + kg * 8;

            unsigned long long wv[4];
#pragma unroll
            for (int c = 0; c < 4; c++)
                wv[c] = *(const unsigned long long*)(wsb + c * 512);

            unsigned long long xv[4];
#pragma unroll
            for (int s = 0; s < 4; s++)
                xv[s] = *(const unsigned long long*)(xs + s * DD + (kidx << 1));
#pragma unroll
            for (int c = 0; c < 4; c++)
#pragma unroll
                for (int s = 0; s < 4; s++)
                    acc[s][c] = ffma2(xv[s], wv[c], acc[s][c]);
#pragma unroll
            for (int s = 0; s < 4; s++)
                xv[s] = *(const unsigned long long*)(xs + (s + 4) * DD + (kidx << 1));
#pragma unroll
            for (int c = 0; c < 4; c++)
#pragma unroll
                for (int s = 0; s < 4; s++)
                    acc[s + 4][c] = ffma2(xv[s], wv[c], acc[s + 4][c]);
        }
        __syncthreads();
        if (j < 4) issue_stage(wb, Wrow0, j + 4, tid);
    }

    // horizontal add (even-k + odd-k), conflict-free partial store into red
    // (aliases dead W stages): bank (idx + kg) % 32, all distinct per phase
#pragma unroll
    for (int s = 0; s < 8; s++) {
#pragma unroll
        for (int c = 0; c < 4; c++) {
            const unsigned long long v = acc[s][c];
            const float lo = __uint_as_float((unsigned)(v & 0xffffffffu));
            const float hi = __uint_as_float((unsigned)(v >> 32));
            red[(s * 32 + cg * 4 + c) * 65 + kg] = lo + hi;
        }
    }
    __syncthreads();

    if (tid < 256) {
        const int s  = tid >> 5;
        const int cp = tid & 31;
        const float* r = red + tid * 65;
        float a0 = 0.f, a1 = 0.f, a2 = 0.f, a3 = 0.f;
#pragma unroll
        for (int k = 0; k < 64; k += 4) {
            a0 += r[k]; a1 += r[k + 1]; a2 += r[k + 2]; a3 += r[k + 3];
        }
        const float sum = (a0 + a1) + (a2 + a3);
        if (s0 + s < cnt)
            out[(size_t)s_bidx[s] * DD + c0 + cp] = s_gvl[s] * sum + bias[c0 + cp];
    }
}

// ---------------------------------------------------------------------------
extern "C" void kernel_launch(void* const* d_in, const int* in_sizes, int n_in,
                              void* d_out, int out_size)
{
    (void)in_sizes; (void)n_in; (void)out_size;
    const float* x    = (const float*)d_in[0];
    const float* gw   = (const float*)d_in[1];
    const float* gb   = (const float*)d_in[2];
    const float* W    = (const float*)d_in[3];
    const float* bias = (const float*)d_in[4];
    float* out = (float*)d_out;

    static int smem_set = 0;
    if (!smem_set) {
        cudaFuncSetAttribute(main_kernel,
                             cudaFuncAttributeMaxDynamicSharedMemorySize,
                             196608);        // 64 KB xs + 128 KB W stages
        smem_set = 1;
    }

    gate_kernel<<<dim3(32, 4), 256>>>(x, gw, gb, bias, out);
    main_kernel<<<256, 512, 196608>>>(x, W, bias, out);
}

// round 15
// speedup vs baseline: 1.5710x; 1.0861x over previous
#include <cuda_runtime.h>
#include <cstdint>

#define DD    2048
#define NBLK  16
#define BATCH 32

// Scratch (no allocations allowed -> __device__ globals; protocol-reset)
__device__ float g_part[BATCH * 4 * NBLK];   // gate logit partials
__device__ int   g_arrive = 0;               // arrival counter (reset by finalize)
__device__ int   g_cnt[NBLK];
__device__ int   g_idx[NBLK * 32];
__device__ float g_gval[NBLK * 32];

// ---------------------------------------------------------------------------
// Kernel 1: gate logit partials, K split 4 ways. grid=(32 batches, 4 slices).
// Bias-fills out. Last-arriving CTA finalizes gates + compaction. (Proven.)
// ---------------------------------------------------------------------------
__global__ __launch_bounds__(256) void gate_kernel(
    const float* __restrict__ x, const float* __restrict__ gw,
    const float* __restrict__ gb, const float* __restrict__ bias,
    float* __restrict__ out)
{
    const int b    = blockIdx.x;
    const int sl   = blockIdx.y;
    const int tid  = threadIdx.x;
    const int base = sl * 512;

    __shared__ int lastflag;
    if (tid == 0) lastflag = 0;

    if (tid < 128)
        ((float4*)(out + (size_t)b * DD + base))[tid] = ((const float4*)(bias + base))[tid];

    float p[NBLK];
#pragma unroll
    for (int j = 0; j < NBLK; j++) p[j] = 0.f;

#pragma unroll
    for (int r = 0; r < 2; r++) {
        const int k = base + r * 256 + tid;
        const float xv = x[(size_t)b * DD + k];
        const float4* gr = (const float4*)(gw + (size_t)k * NBLK);
        const float4 w0 = gr[0], w1 = gr[1], w2 = gr[2], w3 = gr[3];
        p[0]  += xv * w0.x;  p[1]  += xv * w0.y;  p[2]  += xv * w0.z;  p[3]  += xv * w0.w;
        p[4]  += xv * w1.x;  p[5]  += xv * w1.y;  p[6]  += xv * w1.z;  p[7]  += xv * w1.w;
        p[8]  += xv * w2.x;  p[9]  += xv * w2.y;  p[10] += xv * w2.z;  p[11] += xv * w2.w;
        p[12] += xv * w3.x;  p[13] += xv * w3.y;  p[14] += xv * w3.z;  p[15] += xv * w3.w;
    }

#pragma unroll
    for (int j = 0; j < NBLK; j++)
#pragma unroll
        for (int off = 16; off > 0; off >>= 1)
            p[j] += __shfl_xor_sync(0xffffffffu, p[j], off);

    __shared__ float ws[8][NBLK + 1];
    if ((tid & 31) == 0) {
#pragma unroll
        for (int j = 0; j < NBLK; j++) ws[tid >> 5][j] = p[j];
    }
    __syncthreads();

    if (tid < NBLK) {
        float s = 0.f;
#pragma unroll
        for (int w = 0; w < 8; w++) s += ws[w][tid];
        g_part[((size_t)b * 4 + sl) * NBLK + tid] = s;
    }
    __syncthreads();

    if (tid == 0) {
        __threadfence();
        if (atomicAdd(&g_arrive, 1) == 127) lastflag = 1;
    }
    __syncthreads();
    if (!lastflag) return;
    __threadfence();

    __shared__ float sgate[BATCH][NBLK + 1];
    if (tid < BATCH) {
        float v[NBLK];
        const float4* gb4 = (const float4*)gb;
        {
            const float4 b0 = gb4[0], b1 = gb4[1], b2 = gb4[2], b3 = gb4[3];
            v[0]=b0.x;  v[1]=b0.y;  v[2]=b0.z;  v[3]=b0.w;
            v[4]=b1.x;  v[5]=b1.y;  v[6]=b1.z;  v[7]=b1.w;
            v[8]=b2.x;  v[9]=b2.y;  v[10]=b2.z; v[11]=b2.w;
            v[12]=b3.x; v[13]=b3.y; v[14]=b3.z; v[15]=b3.w;
        }
#pragma unroll
        for (int s = 0; s < 4; s++) {
            const float4* pp = (const float4*)(g_part + ((size_t)tid * 4 + s) * NBLK);
            const float4 p0 = pp[0], p1 = pp[1], p2 = pp[2], p3 = pp[3];
            v[0]+=p0.x;  v[1]+=p0.y;  v[2]+=p0.z;  v[3]+=p0.w;
            v[4]+=p1.x;  v[5]+=p1.y;  v[6]+=p1.z;  v[7]+=p1.w;
            v[8]+=p2.x;  v[9]+=p2.y;  v[10]+=p2.z; v[11]+=p2.w;
            v[12]+=p3.x; v[13]+=p3.y; v[14]+=p3.z; v[15]+=p3.w;
        }
#pragma unroll
        for (int j = 0; j < NBLK; j++) v[j] = 1.f / (1.f + expf(-v[j]));

        unsigned mask = 0;   // drop 8 smallest; '<' => lowest index wins ties
        for (int it = 0; it < NBLK / 2; it++) {
            int best = 0; float bv = 3.4e38f;
            for (int j = 0; j < NBLK; j++)
                if (!((mask >> j) & 1u) && v[j] < bv) { bv = v[j]; best = j; }
            mask |= 1u << best;
        }
#pragma unroll
        for (int j = 0; j < NBLK; j++)
            sgate[tid][j] = ((mask >> j) & 1u) ? 0.f : v[j];
    }
    __syncthreads();

    if (tid < 32) {
        const int lane = tid;
        if (lane < NBLK) {
            int cnt = 0;
            for (int bb = 0; bb < BATCH; bb++) {
                const float v = sgate[bb][lane];
                if (v != 0.f) { g_idx[lane * 32 + cnt] = bb; g_gval[lane * 32 + cnt] = v; cnt++; }
            }
            g_cnt[lane] = cnt;
            for (int s = cnt; s < 32; s++) { g_idx[lane * 32 + s] = 0; g_gval[lane * 32 + s] = 0.f; }
        }
        if (lane == 0) g_arrive = 0;         // reset for next graph replay
    }
}

// ---------------------------------------------------------------------------
// Kernel 2: gated skinny GEMM, f32x2 FFMA.
// Small tile -> <=64 regs -> 2 CTAs/SM, 8 warps/SMSP for latency hiding.
// grid=512: tile = bid&63 (32 rows), chunk = bid>>6 (4 compacted slots).
// ---------------------------------------------------------------------------
__device__ __forceinline__ unsigned long long ffma2(
    unsigned long long a, unsigned long long b, unsigned long long c)
{
    unsigned long long d;
    asm("fma.rn.f32x2 %0, %1, %2, %3;" : "=l"(d) : "l"(a), "l"(b), "l"(c));
    return d;
}

__global__ __launch_bounds__(512, 2) void main_kernel(
    const float* __restrict__ x, const float* __restrict__ W,
    const float* __restrict__ bias, float* __restrict__ out)
{
    extern __shared__ float smem[];
    float* xs  = smem;              // 4 rows x 2048 floats (32 KB)
    float* red = smem;              // aliased after loop: 128 x 65 floats (33 KB)

    const int bid  = blockIdx.x;
    const int tid  = threadIdx.x;
    const int tile = bid & 63;
    const int chnk = bid >> 6;           // 0..7
    const int nb   = tile >> 2;
    const int c0   = tile * 32;
    const int s0   = chnk * 4;           // first compacted slot (4 per chunk)

    __shared__ int   s_bidx[4];
    __shared__ float s_gvl[4];
    __shared__ int   s_cnt;
    if (tid < 4) {
        s_bidx[tid] = g_idx[nb * 32 + s0 + tid];   // padded slots: b=0
        s_gvl[tid]  = g_gval[nb * 32 + s0 + tid];
        if (tid == 0) s_cnt = g_cnt[nb];
    }
    __syncthreads();
    const int cnt = s_cnt;
    if (s0 >= cnt) return;               // idle chunk -> outputs stay = bias

    int bidx[4];
#pragma unroll
    for (int j = 0; j < 4; j++) bidx[j] = s_bidx[j];

    // stage x rows (coalesced float4 copies): 4 rows x 512 float4
    for (int m = tid; m < 2048; m += 512) {
        const int s  = m >> 9;
        const int k4 = m & 511;
        ((float4*)(xs + s * DD))[k4] = ((const float4*)(x + (size_t)bidx[s] * DD))[k4];
    }
    __syncthreads();

    const int kg = tid & 63;             // 0..63 (lanes contiguous in k)
    const int cg = tid >> 6;             // 0..7 col-groups x 4 cols = 32 rows

    // W rows for this thread's 4 output columns, viewed as k-pair (u64) stream
    const unsigned long long* w64 =
        (const unsigned long long*)(W + (size_t)(c0 + cg * 4) * DD);

    unsigned long long acc[4][4];
#pragma unroll
    for (int s = 0; s < 4; s++)
#pragma unroll
        for (int c = 0; c < 4; c++) acc[s][c] = 0ull;

    unsigned long long wA[4], wB[4];
#pragma unroll
    for (int c = 0; c < 4; c++) wA[c] = w64[c * 1024 + kg];

#pragma unroll
    for (int i = 0; i < 16; i++) {
        const int kidx = kg + i * 64;                 // k-pair index (k = 2*kidx)
        const int nidx = (kidx + 64) & 1023;          // next iter (wrap harmless)
#pragma unroll
        for (int c = 0; c < 4; c++) wB[c] = w64[c * 1024 + nidx];   // prefetch

        unsigned long long xv[4];
#pragma unroll
        for (int s = 0; s < 4; s++)
            xv[s] = *(const unsigned long long*)(xs + s * DD + (kidx << 1));

#pragma unroll
        for (int c = 0; c < 4; c++) {
            const unsigned long long wv = wA[c];
#pragma unroll
            for (int s = 0; s < 4; s++)
                acc[s][c] = ffma2(xv[s], wv, acc[s][c]);
        }
#pragma unroll
        for (int c = 0; c < 4; c++) wA[c] = wB[c];
    }
    __syncthreads();                     // xs dead; alias as reduction buffer

    // horizontal add (even-k + odd-k), conflict-free partial store:
    // red[(s*32 + cg*4 + c)*65 + kg] -> bank (idx + kg) % 32, all distinct
#pragma unroll
    for (int s = 0; s < 4; s++) {
#pragma unroll
        for (int c = 0; c < 4; c++) {
            const unsigned long long v = acc[s][c];
            const float lo = __uint_as_float((unsigned)(v & 0xffffffffu));
            const float hi = __uint_as_float((unsigned)(v >> 32));
            red[(s * 32 + cg * 4 + c) * 65 + kg] = lo + hi;
        }
    }
    __syncthreads();

    if (tid < 128) {
        const int s  = tid >> 5;         // local slot 0..3
        const int cp = tid & 31;         // local col 0..31
        const float* r = red + tid * 65;
        float a0 = 0.f, a1 = 0.f, a2 = 0.f, a3 = 0.f;
#pragma unroll
        for (int k = 0; k < 64; k += 4) {
            a0 += r[k]; a1 += r[k + 1]; a2 += r[k + 2]; a3 += r[k + 3];
        }
        const float sum = (a0 + a1) + (a2 + a3);
        if (s0 + s < cnt)
            out[(size_t)s_bidx[s] * DD + c0 + cp] = s_gvl[s] * sum + bias[c0 + cp];
    }
}

// ---------------------------------------------------------------------------
extern "C" void kernel_launch(void* const* d_in, const int* in_sizes, int n_in,
                              void* d_out, int out_size)
{
    (void)in_sizes; (void)n_in; (void)out_size;
    const float* x    = (const float*)d_in[0];
    const float* gw   = (const float*)d_in[1];
    const float* gb   = (const float*)d_in[2];
    const float* W    = (const float*)d_in[3];
    const float* bias = (const float*)d_in[4];
    float* out = (float*)d_out;

    static int smem_set = 0;
    if (!smem_set) {
        cudaFuncSetAttribute(main_kernel,
                             cudaFuncAttributeMaxDynamicSharedMemorySize,
                             128 * 65 * 4);   // 33280 B (xs 32 KB aliased inside)
        smem_set = 1;
    }

    gate_kernel<<<dim3(32, 4), 256>>>(x, gw, gb, bias, out);
    main_kernel<<<512, 512, 128 * 65 * 4>>>(x, W, bias, out);
}